// round 1
// baseline (speedup 1.0000x reference)
#include <cuda_runtime.h>

#define NE    8192   // num edges
#define DIM   128
#define PMAX  5
#define NNODE 512

// Scratch for precomputed dot products, layout [p][e] so the 5 lookups of one
// pair go to 5 independent 32KB regions.
__device__ float g_dots[PMAX * NE];

// ---------------------------------------------------------------------------
// Kernel 1: dots[p][e] = sum_d emb[e][d] * ev[p][d]
// Warp per edge: lane handles 4 contiguous dims (float4), butterfly reduce.
// ---------------------------------------------------------------------------
__global__ void edge_dot_kernel(const float* __restrict__ emb,
                                const float* __restrict__ ev) {
    const int lane   = threadIdx.x & 31;
    const int warp   = (blockIdx.x * blockDim.x + threadIdx.x) >> 5;
    const int nwarps = (gridDim.x * blockDim.x) >> 5;

    // edge_vector: 5 x 128 floats, each lane keeps its 4-dim slice of all 5 rows
    float4 evr[PMAX];
#pragma unroll
    for (int p = 0; p < PMAX; ++p)
        evr[p] = __ldg(((const float4*)ev) + p * (DIM / 4) + lane);

    for (int e = warp; e < NE; e += nwarps) {
        float4 a = __ldg(((const float4*)emb) + e * (DIM / 4) + lane);
        float part[PMAX];
#pragma unroll
        for (int p = 0; p < PMAX; ++p)
            part[p] = a.x * evr[p].x + a.y * evr[p].y +
                      a.z * evr[p].z + a.w * evr[p].w;
#pragma unroll
        for (int off = 16; off > 0; off >>= 1) {
#pragma unroll
            for (int p = 0; p < PMAX; ++p)
                part[p] += __shfl_xor_sync(0xffffffffu, part[p], off);
        }
        if (lane == 0) {
            g_dots[0 * NE + e] = part[0];
            g_dots[1 * NE + e] = part[1];
            g_dots[2 * NE + e] = part[2];
            g_dots[3 * NE + e] = part[3];
            g_dots[4 * NE + e] = part[4];
        }
    }
}

// ---------------------------------------------------------------------------
// Kernel 2: per (i,j) pair, sum dots[p][e_p] over non-padded positions, / len.
// Persistent CTAs; dots table staged into 160KB shared memory once per CTA.
// ---------------------------------------------------------------------------
__global__ void gather_kernel(const int* __restrict__ paths,
                              float* __restrict__ out,
                              int total) {
    extern __shared__ float s_dots[];   // PMAX*NE floats = 163840 bytes

    // Fill shared table (float4 vectorized)
    {
        const float4* src = (const float4*)g_dots;
        float4*       dst = (float4*)s_dots;
        const int nvec = PMAX * NE / 4;
        for (int i = threadIdx.x; i < nvec; i += blockDim.x)
            dst[i] = src[i];
    }
    __syncthreads();

    const int stride = gridDim.x * blockDim.x;
    for (int idx = blockIdx.x * blockDim.x + threadIdx.x; idx < total;
         idx += stride) {
        const int* pp = paths + idx * PMAX;
        float acc = 0.0f;
        int   cnt = 0;
#pragma unroll
        for (int p = 0; p < PMAX; ++p) {
            int e = __ldg(pp + p);
            if (e >= 0) {
                acc += s_dots[p * NE + e];
                ++cnt;
            }
        }
        out[idx] = cnt ? acc * (1.0f / (float)cnt) : 0.0f;
    }
}

// ---------------------------------------------------------------------------
// Launch
// ---------------------------------------------------------------------------
extern "C" void kernel_launch(void* const* d_in, const int* in_sizes, int n_in,
                              void* d_out, int out_size) {
    // Identify inputs by element count (robust to ordering):
    //   x:             512*128   = 65536   (unused)
    //   edge_embedding 8192*128  = 1048576
    //   edge_paths     512*512*5 = 1310720
    //   edge_vector    5*128     = 640
    const float* emb   = nullptr;
    const int*   paths = nullptr;
    const float* ev    = nullptr;
    for (int i = 0; i < n_in; ++i) {
        if (in_sizes[i] == NE * DIM)            emb   = (const float*)d_in[i];
        else if (in_sizes[i] == NNODE * NNODE * PMAX) paths = (const int*)d_in[i];
        else if (in_sizes[i] == PMAX * DIM)     ev    = (const float*)d_in[i];
    }
    float* out = (float*)d_out;

    edge_dot_kernel<<<256, 256>>>(emb, ev);

    const int smem_bytes = PMAX * NE * (int)sizeof(float);  // 163840
    cudaFuncSetAttribute(gather_kernel,
                         cudaFuncAttributeMaxDynamicSharedMemorySize,
                         smem_bytes);
    gather_kernel<<<148, 1024, smem_bytes>>>(paths, out, out_size);
}

// round 2
// speedup vs baseline: 1.1860x; 1.1860x over previous
#include <cuda_runtime.h>
#include <cstdint>

#define NE    8192   // num edges
#define DIM   128
#define PMAX  5
#define NNODE 512
#define TOTAL (NNODE * NNODE)
#define TBL_BYTES (PMAX * NE * 4)   // 163840

// Precomputed dot products, layout [p][e].
__device__ float g_dots[PMAX * NE];

__device__ __forceinline__ uint32_t smem_u32(const void* p) {
    return (uint32_t)__cvta_generic_to_shared(p);
}

// ---------------------------------------------------------------------------
// Kernel 1: dots[p][e] = sum_d emb[e][d] * ev[p][d]
// One warp per edge (8192 warps total), float4 lanes + butterfly reduce.
// ---------------------------------------------------------------------------
__global__ __launch_bounds__(1024) void edge_dot_kernel(
        const float* __restrict__ emb, const float* __restrict__ ev) {
    const int lane = threadIdx.x & 31;
    const int e    = (blockIdx.x * blockDim.x + threadIdx.x) >> 5;
    if (e >= NE) return;

    float4 evr[PMAX];
#pragma unroll
    for (int p = 0; p < PMAX; ++p)
        evr[p] = __ldg(((const float4*)ev) + p * (DIM / 4) + lane);

    float4 a = __ldg(((const float4*)emb) + e * (DIM / 4) + lane);

    float part[PMAX];
#pragma unroll
    for (int p = 0; p < PMAX; ++p)
        part[p] = a.x * evr[p].x + a.y * evr[p].y +
                  a.z * evr[p].z + a.w * evr[p].w;

#pragma unroll
    for (int off = 16; off > 0; off >>= 1) {
#pragma unroll
        for (int p = 0; p < PMAX; ++p)
            part[p] += __shfl_xor_sync(0xffffffffu, part[p], off);
    }

    if (lane == 0) {
#pragma unroll
        for (int p = 0; p < PMAX; ++p)
            g_dots[p * NE + e] = part[p];
    }
}

// ---------------------------------------------------------------------------
// Kernel 2: per (i,j) pair, sum dots[p][e_p] over non-padded positions, / len.
// 128 CTAs x 1024 threads x 2 pairs = 262144 exactly.
// Path indices prefetched into registers BEFORE the smem table fill; table
// filled with cp.async.bulk so the two latency chains overlap.
// ---------------------------------------------------------------------------
__global__ __launch_bounds__(1024, 1) void gather_kernel(
        const int* __restrict__ paths, float* __restrict__ out) {
    extern __shared__ float s_dots[];               // 163840 bytes
    __shared__ __align__(8) unsigned long long mbar;

    const int tid    = threadIdx.x;
    const int stride = gridDim.x * blockDim.x;      // 131072
    const int idx0   = blockIdx.x * blockDim.x + tid;
    const int idx1   = idx0 + stride;

    // --- prefetch path indices (DRAM latency hides under the table fill) ---
    int e0[PMAX], e1[PMAX];
#pragma unroll
    for (int p = 0; p < PMAX; ++p) e0[p] = __ldg(paths + idx0 * PMAX + p);
#pragma unroll
    for (int p = 0; p < PMAX; ++p) e1[p] = __ldg(paths + idx1 * PMAX + p);

    // --- bulk-copy the dots table into shared memory ---
    const uint32_t mb = smem_u32(&mbar);
    if (tid == 0) {
        asm volatile("mbarrier.init.shared.b64 [%0], 1;" :: "r"(mb));
    }
    __syncthreads();
    if (tid == 0) {
        asm volatile("mbarrier.arrive.expect_tx.shared.b64 _, [%0], %1;"
                     :: "r"(mb), "r"((uint32_t)TBL_BYTES) : "memory");
        uint32_t    dst = smem_u32(s_dots);
        const char* src = (const char*)g_dots;
#pragma unroll
        for (int c = 0; c < 4; ++c) {
            asm volatile(
                "cp.async.bulk.shared::cta.global.mbarrier::complete_tx::bytes "
                "[%0], [%1], %2, [%3];"
                :: "r"(dst + c * (TBL_BYTES / 4)),
                   "l"(src + c * (TBL_BYTES / 4)),
                   "r"((uint32_t)(TBL_BYTES / 4)), "r"(mb)
                : "memory");
        }
    }
    // wait (parity 0), acquire so the smem reads below are ordered
    {
        uint32_t done;
        asm volatile(
            "{\n\t.reg .pred p;\n\t"
            "mbarrier.try_wait.parity.acquire.cta.shared::cta.b64 p, [%1], 0;\n\t"
            "selp.b32 %0, 1, 0, p;\n\t}"
            : "=r"(done) : "r"(mb) : "memory");
        while (!done) {
            asm volatile(
                "{\n\t.reg .pred p;\n\t"
                "mbarrier.try_wait.parity.acquire.cta.shared::cta.b64 p, [%1], 0, 0x989680;\n\t"
                "selp.b32 %0, 1, 0, p;\n\t}"
                : "=r"(done) : "r"(mb) : "memory");
        }
    }

    // --- gather + reduce ---
    {
        float acc = 0.0f; int cnt = 0;
#pragma unroll
        for (int p = 0; p < PMAX; ++p) {
            int e = e0[p];
            if (e >= 0) { acc += s_dots[p * NE + e]; ++cnt; }
        }
        out[idx0] = cnt ? acc / (float)cnt : 0.0f;
    }
    {
        float acc = 0.0f; int cnt = 0;
#pragma unroll
        for (int p = 0; p < PMAX; ++p) {
            int e = e1[p];
            if (e >= 0) { acc += s_dots[p * NE + e]; ++cnt; }
        }
        out[idx1] = cnt ? acc / (float)cnt : 0.0f;
    }
}

// ---------------------------------------------------------------------------
// Launch
// ---------------------------------------------------------------------------
extern "C" void kernel_launch(void* const* d_in, const int* in_sizes, int n_in,
                              void* d_out, int out_size) {
    const float* emb   = nullptr;
    const int*   paths = nullptr;
    const float* ev    = nullptr;
    for (int i = 0; i < n_in; ++i) {
        if (in_sizes[i] == NE * DIM)                  emb   = (const float*)d_in[i];
        else if (in_sizes[i] == NNODE * NNODE * PMAX) paths = (const int*)d_in[i];
        else if (in_sizes[i] == PMAX * DIM)           ev    = (const float*)d_in[i];
    }
    float* out = (float*)d_out;

    // 8192 warps = 8192 edges, one shot
    edge_dot_kernel<<<256, 1024>>>(emb, ev);

    const int smem_bytes = TBL_BYTES;
    cudaFuncSetAttribute(gather_kernel,
                         cudaFuncAttributeMaxDynamicSharedMemorySize,
                         smem_bytes);
    gather_kernel<<<128, 1024, smem_bytes>>>(paths, out);
}